// round 4
// baseline (speedup 1.0000x reference)
#include <cuda_runtime.h>

// ---------------------------------------------------------------------------
// SelfInteraction: N=50000 rows, MUL0=64 scalars, MUL1=32 3-vectors.
//
// Restructured math (constants folded into prepped weights):
//   f[p]   = s_u*s_v (2080 sym pairs) | v_u.v_v (528 sym pairs)   per row
//   out_s  = f @ WS            (WS: 2624x64, padded, c0 / c0*inv_sqrt3 folded)
//   T[j]   = s @ CW            (CW: 64x1024, j = m*32+w, 1/64 folded)
//   out_v[w,i] = sum_m T[m*32+w] * v[m,i]
// ---------------------------------------------------------------------------

#define M0     64
#define M1     32
#define XW     160
#define NP0    2080        // 64*65/2 s-pairs
#define NP     2608        // + 32*33/2 v-pairs
#define NPP    2624        // padded to 41*64
#define NCHUNK 41
#define RBLK   64

// smem layout (floats)
#define SVS     161                    // row stride for staged x rows
#define SV_SZ   (RBLK*SVS)             // 10304
#define FTS     68                     // fT stride (float4-aligned, low conflict)
#define FT_OFF  SV_SZ                  // 10304
#define WS_OFF  (FT_OFF + 64*FTS)      // 14656
#define CWSTR   132
#define CW_OFF  SV_SZ                  // 10304 (aliases phase-B region)
#define TC_OFF  (SV_SZ + 64*CWSTR)     // 18752
#define SMEM_FLOATS (TC_OFF + 64*CWSTR) // 27200 floats = 108800 B

__device__ float g_WS[NPP*64];   // 656 KB
__device__ float g_CW[64*1024];  // 256 KB
__device__ int   g_pairs[NPP];

// ------------------------- prep kernels (run each launch, ~us) -------------

__global__ void prep_pairs_k() {
    int p = blockIdx.x*256 + threadIdx.x;
    if (p >= NPP) return;
    int offA = 0, offB = 0, typ = 0;
    if (p < NP0) {
        int rem = p, u = 0;
        while (rem >= M0 - u) { rem -= M0 - u; u++; }
        offA = u; offB = u + rem;
    } else if (p < NP) {
        int rem = p - NP0, u = 0;
        while (rem >= M1 - u) { rem -= M1 - u; u++; }
        offA = M0 + 3*u; offB = M0 + 3*(u + rem); typ = 1;
    }
    g_pairs[p] = offA | (offB << 8) | (typ << 16);
}

__global__ void prep_ws_k(const float* __restrict__ W000,
                          const float* __restrict__ W110) {
    int idx = blockIdx.x*256 + threadIdx.x;
    if (idx >= NPP*64) return;
    int p = idx >> 6, w = idx & 63;
    const float c0  = 0.013975424859373686f;              // sqrt(1/5120)
    const float c0i = c0 * 0.5773502691896258f;           // c0/sqrt(3)
    float val = 0.f;
    if (p < NP0) {
        int rem = p, u = 0;
        while (rem >= M0 - u) { rem -= M0 - u; u++; }
        int v = u + rem;
        float a = W000[(u*M0 + v)*64 + w];
        if (u != v) a += W000[(v*M0 + u)*64 + w];
        val = c0 * a;
    } else if (p < NP) {
        int rem = p - NP0, u = 0;
        while (rem >= M1 - u) { rem -= M1 - u; u++; }
        int v = u + rem;
        float a = W110[(u*M1 + v)*64 + w];
        if (u != v) a += W110[(v*M1 + u)*64 + w];
        val = c0i * a;
    }
    g_WS[idx] = val;
}

__global__ void prep_cw_k(const float* __restrict__ W011,
                          const float* __restrict__ W101) {
    int idx = blockIdx.x*256 + threadIdx.x;
    if (idx >= 64*1024) return;
    int a = idx >> 10, j = idx & 1023;
    int m = j >> 5, w = j & 31;
    // c1*inv_sqrt3 = sqrt(3/4096)/sqrt(3) = 1/64
    g_CW[idx] = 0.015625f * (W011[idx] + W101[m*2048 + a*32 + w]);
}

// ------------------------- main fused kernel --------------------------------

extern __shared__ float smem[];

__global__ void __launch_bounds__(256, 2)
si_main_k(const float* __restrict__ x, float* __restrict__ out, int nrows)
{
    const int t    = threadIdx.x;
    const int row0 = blockIdx.x * RBLK;
    float* sv = smem;

    // Phase A: stage 64 rows of x (zero-fill past end)
    for (int idx = t; idx < RBLK*XW; idx += 256) {
        int r = idx / XW, c = idx - r*XW;
        int row = row0 + r;
        sv[r*SVS + c] = (row < nrows) ? x[(size_t)row*XW + c] : 0.f;
    }
    __syncthreads();

    // ---- Phase B: out_s = f @ WS ----
    {
        float* fT  = smem + FT_OFF;
        float* wsS = smem + WS_OFF;
        const int tx = t & 15, ty = t >> 4;      // cols tx*4..+3, rows ty*4..+3
        const int p_local = t & 63;
        const int rgrp = (t >> 6) * 16;
        const float* fp = fT  + ty*4;
        const float* wp = wsS + tx*4;

        float acc[4][4];
        #pragma unroll
        for (int a = 0; a < 4; a++)
            #pragma unroll
            for (int b = 0; b < 4; b++) acc[a][b] = 0.f;

        for (int ch = 0; ch < NCHUNK; ch++) {
            // stage WS tile [64 p][64 w] (contiguous in g_WS)
            const float4* wsrc = (const float4*)(g_WS + ch*4096);
            float4* wdst = (float4*)wsS;
            #pragma unroll
            for (int k = 0; k < 4; k++)
                wdst[t + k*256] = wsrc[t + k*256];

            // form f tile: this thread does pair p_local for 16 rows
            int packed = g_pairs[ch*64 + p_local];
            int offA = packed & 255, offB = (packed >> 8) & 255;
            float* fdst = fT + p_local*FTS;
            const float* svA = sv + offA;
            const float* svB = sv + offB;
            if (packed < (1 << 16)) {            // scalar pair
                #pragma unroll
                for (int q = 0; q < 16; q++) {
                    int r = rgrp + q;
                    fdst[r] = svA[r*SVS] * svB[r*SVS];
                }
            } else {                             // vector pair: 3-dot
                #pragma unroll
                for (int q = 0; q < 16; q++) {
                    int r = rgrp + q;
                    const float* a = svA + r*SVS;
                    const float* b = svB + r*SVS;
                    fdst[r] = a[0]*b[0] + a[1]*b[1] + a[2]*b[2];
                }
            }
            __syncthreads();

            // 4x4 register-tiled GEMM over this 64-p chunk
            #pragma unroll 8
            for (int pc = 0; pc < 64; pc++) {
                float4 w4 = *(const float4*)(wp + pc*64);
                float4 f4 = *(const float4*)(fp + pc*FTS);
                acc[0][0] += f4.x*w4.x; acc[0][1] += f4.x*w4.y;
                acc[0][2] += f4.x*w4.z; acc[0][3] += f4.x*w4.w;
                acc[1][0] += f4.y*w4.x; acc[1][1] += f4.y*w4.y;
                acc[1][2] += f4.y*w4.z; acc[1][3] += f4.y*w4.w;
                acc[2][0] += f4.z*w4.x; acc[2][1] += f4.z*w4.y;
                acc[2][2] += f4.z*w4.z; acc[2][3] += f4.z*w4.w;
                acc[3][0] += f4.w*w4.x; acc[3][1] += f4.w*w4.y;
                acc[3][2] += f4.w*w4.z; acc[3][3] += f4.w*w4.w;
            }
            __syncthreads();
        }

        #pragma unroll
        for (int k = 0; k < 4; k++) {
            int row = row0 + ty*4 + k;
            if (row < nrows) {
                *(float4*)(out + (size_t)row*XW + tx*4) =
                    make_float4(acc[k][0], acc[k][1], acc[k][2], acc[k][3]);
            }
        }
    }

    // ---- Phase C: T = s @ CW, then out_v ----
    {
        float* cwS = smem + CW_OFF;
        float* TcS = smem + TC_OFF;
        const int txc = t & 15, tyc = t >> 4;    // T-cols txc*8..+7, rows tyc*4..+3
        const int rown  = t >> 2;                // out_v row ownership
        const int cbase = (t & 3) * 24;          // 24 of 96 out_v cols
        float ov[24];
        #pragma unroll
        for (int k = 0; k < 24; k++) ov[k] = 0.f;

        for (int jc = 0; jc < 8; jc++) {         // 128 T-cols (= 4 m values) per chunk
            __syncthreads();                     // prior reads of cwS/TcS done
            // stage CW tile [64 a][128 j]
            #pragma unroll
            for (int k = 0; k < 8; k++) {
                int idx = t + k*256;             // 0..2047 float4s
                int a = idx >> 5, jj = idx & 31;
                *(float4*)(cwS + a*CWSTR + jj*4) =
                    *(const float4*)(g_CW + a*1024 + jc*128 + jj*4);
            }
            __syncthreads();

            // GEMM: Tc[64 r][128 j] = sv_s(64x64) @ cw(64x128), 4x8 tiles
            float accC[4][8];
            #pragma unroll
            for (int a = 0; a < 4; a++)
                #pragma unroll
                for (int b = 0; b < 8; b++) accC[a][b] = 0.f;

            #pragma unroll 4
            for (int a = 0; a < 64; a++) {
                float4 b0 = *(const float4*)(cwS + a*CWSTR + txc*8);
                float4 b1 = *(const float4*)(cwS + a*CWSTR + txc*8 + 4);
                #pragma unroll
                for (int k = 0; k < 4; k++) {
                    float s = sv[(tyc*4 + k)*SVS + a];
                    accC[k][0] += s*b0.x; accC[k][1] += s*b0.y;
                    accC[k][2] += s*b0.z; accC[k][3] += s*b0.w;
                    accC[k][4] += s*b1.x; accC[k][5] += s*b1.y;
                    accC[k][6] += s*b1.z; accC[k][7] += s*b1.w;
                }
            }
            #pragma unroll
            for (int k = 0; k < 4; k++) {
                float* dst = TcS + (tyc*4 + k)*CWSTR + txc*8;
                *(float4*)dst       = make_float4(accC[k][0], accC[k][1], accC[k][2], accC[k][3]);
                *(float4*)(dst + 4) = make_float4(accC[k][4], accC[k][5], accC[k][6], accC[k][7]);
            }
            __syncthreads();

            // out_v partial: m in [jc*4, jc*4+4)
            const float* Trow = TcS + rown*CWSTR;
            const float* vrow = sv + rown*SVS + M0 + jc*4*3;
            #pragma unroll
            for (int k = 0; k < 24; k++) {
                int c = cbase + k;
                int w = c / 3;
                int i = c - 3*w;
                float sacc = 0.f;
                #pragma unroll
                for (int dm = 0; dm < 4; dm++)
                    sacc += Trow[dm*32 + w] * vrow[dm*3 + i];
                ov[k] += sacc;
            }
        }

        int row = row0 + rown;
        if (row < nrows) {
            float* o = out + (size_t)row*XW + M0 + cbase;
            #pragma unroll
            for (int k = 0; k < 24; k += 4)
                *(float4*)(o + k) = make_float4(ov[k], ov[k+1], ov[k+2], ov[k+3]);
        }
    }
}

// ------------------------- launch ------------------------------------------

extern "C" void kernel_launch(void* const* d_in, const int* in_sizes, int n_in,
                              void* d_out, int out_size)
{
    const float* x    = (const float*)d_in[0];
    const float* W000 = (const float*)d_in[1];
    const float* W110 = (const float*)d_in[2];
    const float* W011 = (const float*)d_in[3];
    const float* W101 = (const float*)d_in[4];
    float* out = (float*)d_out;
    const int nrows = in_sizes[0] / XW;

    cudaFuncSetAttribute(si_main_k, cudaFuncAttributeMaxDynamicSharedMemorySize,
                         SMEM_FLOATS * 4);

    prep_pairs_k<<<(NPP + 255)/256, 256>>>();
    prep_ws_k<<<(NPP*64 + 255)/256, 256>>>(W000, W110);
    prep_cw_k<<<(64*1024)/256, 256>>>(W011, W101);

    int grid = (nrows + RBLK - 1) / RBLK;
    si_main_k<<<grid, 256, SMEM_FLOATS * 4>>>(x, out, nrows);
}